// round 13
// baseline (speedup 1.0000x reference)
#include <cuda_runtime.h>

#define MAXN 131072
#define HID  128
#define ODIM 400
#define MAXVB 512           // max k_v blocks (MAXN/256)

// Scratch (no cudaMalloc allowed) — device globals, zeroed at module load.
// Consumers restore the zero-invariant so graph replays are deterministic.
__device__ unsigned g_degi[MAXN];
__device__ float    g_dinv[MAXN];
__device__ float    g_y[MAXN];      // y[r] = dinv[r] * x[r]
__device__ float    g_sacc[MAXN];
__device__ float    g_tacc[MAXN];
__device__ float    g_vpart[MAXVB * HID];   // per-block partials (no atomics)
__device__ unsigned g_vcnt;                 // k_v completion counter

// ---------------------------------------------------------------------------
// 1) degree count over destinations (col). EPT=2: fine-grained blocks for
//    smooth wave tail; int2 coalesced index loads.
__global__ void __launch_bounds__(256, 8)
k_deg(const int* __restrict__ col, int E, int vec_ok) {
    int t = blockIdx.x * blockDim.x + threadIdx.x;
    int e = t * 2;
    if (vec_ok && e + 1 < E) {
        int2 c = *reinterpret_cast<const int2*>(col + e);
        atomicAdd(&g_degi[c.x], 1u);
        atomicAdd(&g_degi[c.y], 1u);
    } else if (e < E) {
        int lim = min(e + 2, E);
        for (int k = e; k < lim; k++) atomicAdd(&g_degi[col[k]], 1u);
    }
}

// ---------------------------------------------------------------------------
// 2) dinv = rsqrt(deg + 1 self loop); y = dinv * x; re-zero degi for replay.
__global__ void k_dinv(const float* __restrict__ x, int n) {
    int i = blockIdx.x * blockDim.x + threadIdx.x;
    if (i < n) {
        float di = rsqrtf((float)(g_degi[i] + 1u));
        g_dinv[i] = di;
        g_y[i]    = di * x[i];
        g_degi[i] = 0u;                 // restore entry invariant
    }
}

// ---------------------------------------------------------------------------
// 3) fused edge pass: independent gathers + fire-and-forget REDs.
//    sacc[c] += y[r];  tacc[r] += dinv[c]
//    EPT=2 -> ~3125 blocks: finer waves, better tail rebalance.
__global__ void __launch_bounds__(256, 8)
k_edge(const int* __restrict__ row, const int* __restrict__ col,
       int E, int vec_ok) {
    int t = blockIdx.x * blockDim.x + threadIdx.x;
    int e = t * 2;
    if (vec_ok && e + 1 < E) {
        int2 r = *reinterpret_cast<const int2*>(row + e);
        int2 c = *reinterpret_cast<const int2*>(col + e);
        float y0 = __ldg(&g_y[r.x]);
        float y1 = __ldg(&g_y[r.y]);
        float d0 = __ldg(&g_dinv[c.x]);
        float d1 = __ldg(&g_dinv[c.y]);
        atomicAdd(&g_sacc[c.x], y0);
        atomicAdd(&g_sacc[c.y], y1);
        atomicAdd(&g_tacc[r.x], d0);
        atomicAdd(&g_tacc[r.y], d1);
    } else if (e < E) {
        int lim = min(e + 2, E);
        for (int k = e; k < lim; k++) {
            int r = row[k], c = col[k];
            atomicAdd(&g_sacc[c], __ldg(&g_y[r]));
            atomicAdd(&g_tacc[r], __ldg(&g_dinv[c]));
        }
    }
}

// ---------------------------------------------------------------------------
// 4) v[f] = sum_i t[i] * relu(s[i]*W1[f] + b1[f]); fused final reduction +
//    W2 matvec in the LAST block (last-block-done pattern, no extra launch).
//    s[i] = di*(sacc[i] + y[i]);  t[i] = di*(tacc[i] + di)
__global__ void __launch_bounds__(256, 8)
k_v(const float* __restrict__ W1, const float* __restrict__ b1,
    const float* __restrict__ W2, const float* __restrict__ b2,
    float* __restrict__ out, int n, int nbv) {
    __shared__ float2 st[256];          // {s, t} per node in tile
    __shared__ float  red[256];
    const int tid  = threadIdx.x;
    const int f    = tid & (HID - 1);
    const int half = tid >> 7;          // 0 or 1

    // tile load: 256 threads compute (s,t) for 256 nodes
    {
        int i = blockIdx.x * 256 + tid;
        float sv = 0.0f, tv = 0.0f;
        if (i < n) {
            float di = g_dinv[i];
            sv = di * (g_sacc[i] + g_y[i]);
            tv = di * (g_tacc[i] + di);
            g_sacc[i] = 0.0f;           // restore entry invariant
            g_tacc[i] = 0.0f;
        }
        st[tid] = make_float2(sv, tv);
    }
    __syncthreads();

    float w  = W1[f];
    float bb = b1[f];
    float a0 = 0.0f, a1 = 0.0f, a2 = 0.0f, a3 = 0.0f;

    // each half processes 128 nodes: 64 float4 loads = 128 (s,t) pairs
    const float4* stv = reinterpret_cast<const float4*>(st + half * 128);
    #pragma unroll
    for (int k = 0; k < 64; k += 2) {
        float4 p = stv[k];              // {s0,t0,s1,t1}
        float4 q = stv[k + 1];          // {s2,t2,s3,t3}
        float h0 = fmaxf(fmaf(p.x, w, bb), 0.0f);
        float h1 = fmaxf(fmaf(p.z, w, bb), 0.0f);
        float h2 = fmaxf(fmaf(q.x, w, bb), 0.0f);
        float h3 = fmaxf(fmaf(q.z, w, bb), 0.0f);
        a0 = fmaf(p.y, h0, a0);
        a1 = fmaf(p.w, h1, a1);
        a2 = fmaf(q.y, h2, a2);
        a3 = fmaf(q.w, h3, a3);
    }

    red[tid] = (a0 + a1) + (a2 + a3);
    __syncthreads();
    if (tid < 128)
        g_vpart[blockIdx.x * HID + f] = red[tid] + red[tid + 128];

    // ---- last-block-done epilogue (replaces k_out) -----------------------
    __shared__ unsigned s_last;
    __threadfence();                    // make partials visible
    if (tid == 0) {
        unsigned prev = atomicAdd(&g_vcnt, 1u);
        s_last = (prev == (unsigned)(nbv - 1)) ? 1u : 0u;
    }
    __syncthreads();
    if (!s_last) return;

    if (tid == 0) g_vcnt = 0u;          // restore entry invariant
    __threadfence();

    // reduce partials -> v[128]
    __shared__ float vsh[HID];
    float a = 0.0f;
    for (int b = half; b < nbv; b += 2)
        a += g_vpart[b * HID + f];
    red[tid] = a;
    __syncthreads();
    if (tid < HID) vsh[tid] = red[tid] + red[tid + 128];
    __syncthreads();

    // out[o] = (1/n) * sum_f v[f]*W2[f,o] + b2[o]
    for (int o = tid; o < ODIM; o += 256) {
        float acc = 0.0f;
        #pragma unroll 16
        for (int k = 0; k < HID; k++)
            acc = fmaf(vsh[k], W2[k * ODIM + o], acc);
        out[o] = acc * (1.0f / (float)n) + b2[o];
    }
}

// ---------------------------------------------------------------------------
extern "C" void kernel_launch(void* const* d_in, const int* in_sizes, int n_in,
                              void* d_out, int out_size) {
    const float* x  = (const float*)d_in[0];   // [N,1]
    const int*   ei = (const int*)d_in[1];     // [2,E]: row half then col half
    const float* W1 = (const float*)d_in[2];   // [1,128]
    const float* b1 = (const float*)d_in[3];   // [128]
    const float* W2 = (const float*)d_in[4];   // [128,400]
    const float* b2 = (const float*)d_in[5];   // [400]
    float* out = (float*)d_out;                // [400]

    int n = in_sizes[0];
    int E = in_sizes[1] / 2;
    const int* row = ei;
    const int* col = ei + E;
    int vec_ok = ((E & 1) == 0) ? 1 : 0;       // int2 path needs even E

    int nb_n = (n + 255) / 256;
    int eth  = (E + 1) / 2;                    // 2 edges per thread
    int nb_e = (eth + 255) / 256;              // ~3125 blocks: fine-grained waves
    int nb_v = (n + 255) / 256;                // 256-node tiles (<= MAXVB)

    k_deg <<<nb_e, 256>>>(col, E, vec_ok);
    k_dinv<<<nb_n, 256>>>(x, n);
    k_edge<<<nb_e, 256>>>(row, col, E, vec_ok);
    k_v   <<<nb_v, 256>>>(W1, b1, W2, b2, out, n, nb_v);
}

// round 15
// speedup vs baseline: 1.1108x; 1.1108x over previous
#include <cuda_runtime.h>

#define MAXN 131072
#define HID  128
#define ODIM 400
#define MAXVB 512           // max k_v partial rows

// Scratch (no cudaMalloc allowed) — device globals, zeroed at module load.
// Consumers restore the zero-invariant so graph replays are deterministic.
__device__ unsigned g_degi[MAXN];
__device__ float    g_dinv[MAXN];
__device__ float    g_y[MAXN];      // y[r] = dinv[r] * x[r]
__device__ float    g_sacc[MAXN];
__device__ float    g_tacc[MAXN];
__device__ float    g_vpart[MAXVB * HID];   // per-block partials (no atomics)

// ---------------------------------------------------------------------------
// 1) degree count over destinations (col). R7-proven: 4 edges/thread, int4.
__global__ void __launch_bounds__(256, 8)
k_deg(const int* __restrict__ col, int E, int vec_ok) {
    int i = blockIdx.x * blockDim.x + threadIdx.x;
    int e = i * 4;
    if (vec_ok && e + 3 < E) {
        int4 c = *reinterpret_cast<const int4*>(col + e);
        atomicAdd(&g_degi[c.x], 1u);
        atomicAdd(&g_degi[c.y], 1u);
        atomicAdd(&g_degi[c.z], 1u);
        atomicAdd(&g_degi[c.w], 1u);
    } else if (e < E) {
        int lim = min(e + 4, E);
        for (int k = e; k < lim; k++) atomicAdd(&g_degi[col[k]], 1u);
    }
}

// ---------------------------------------------------------------------------
// 2) dinv = rsqrt(deg + 1 self loop); y = dinv * x; re-zero degi for replay.
__global__ void k_dinv(const float* __restrict__ x, int n) {
    int i = blockIdx.x * blockDim.x + threadIdx.x;
    if (i < n) {
        float di = rsqrtf((float)(g_degi[i] + 1u));
        g_dinv[i] = di;
        g_y[i]    = di * x[i];
        g_degi[i] = 0u;                 // restore entry invariant
    }
}

// ---------------------------------------------------------------------------
// 3) fused edge pass (R7-proven): independent gathers + fire-and-forget REDs.
//    sacc[c] += y[r];  tacc[r] += dinv[c]
__global__ void __launch_bounds__(256, 8)
k_edge(const int* __restrict__ row, const int* __restrict__ col,
       int E, int vec_ok) {
    int i = blockIdx.x * blockDim.x + threadIdx.x;
    int e = i * 4;
    if (vec_ok && e + 3 < E) {
        int4 r = *reinterpret_cast<const int4*>(row + e);
        int4 c = *reinterpret_cast<const int4*>(col + e);
        // 8 independent gathers (full MLP, L2-resident), then 8 REDs
        float y0 = __ldg(&g_y[r.x]);
        float y1 = __ldg(&g_y[r.y]);
        float y2 = __ldg(&g_y[r.z]);
        float y3 = __ldg(&g_y[r.w]);
        float d0 = __ldg(&g_dinv[c.x]);
        float d1 = __ldg(&g_dinv[c.y]);
        float d2 = __ldg(&g_dinv[c.z]);
        float d3 = __ldg(&g_dinv[c.w]);
        atomicAdd(&g_sacc[c.x], y0);
        atomicAdd(&g_sacc[c.y], y1);
        atomicAdd(&g_sacc[c.z], y2);
        atomicAdd(&g_sacc[c.w], y3);
        atomicAdd(&g_tacc[r.x], d0);
        atomicAdd(&g_tacc[r.y], d1);
        atomicAdd(&g_tacc[r.z], d2);
        atomicAdd(&g_tacc[r.w], d3);
    } else if (e < E) {
        int lim = min(e + 4, E);
        for (int k = e; k < lim; k++) {
            int r = row[k], c = col[k];
            atomicAdd(&g_sacc[c], __ldg(&g_y[r]));
            atomicAdd(&g_tacc[r], __ldg(&g_dinv[c]));
        }
    }
}

// ---------------------------------------------------------------------------
// 4) v[f] = sum_i t[i] * relu(s[i]*W1[f] + b1[f])  -> per-block partials
//    s[i] = di*(sacc[i] + y[i]);  t[i] = di*(tacc[i] + di)
//    512 threads, 512-node tile per block (grid ~196): 16 warps/block hide
//    the tile-load latency; 4 quarter-tiles of 128 nodes. {s,t} packed
//    float2, read as float4. No global atomics. Out-of-range nodes: t=0.
__global__ void __launch_bounds__(512, 4)
k_v(const float* __restrict__ W1, const float* __restrict__ b1, int n) {
    __shared__ float2 st[512];          // {s, t} per node in tile
    __shared__ float  red[512];
    const int tid = threadIdx.x;
    const int f   = tid & (HID - 1);
    const int qtr = tid >> 7;           // 0..3

    // tile load: 512 threads compute (s,t) for 512 nodes
    {
        int i = blockIdx.x * 512 + tid;
        float sv = 0.0f, tv = 0.0f;
        if (i < n) {
            float di = g_dinv[i];
            sv = di * (g_sacc[i] + g_y[i]);
            tv = di * (g_tacc[i] + di);
            g_sacc[i] = 0.0f;           // restore entry invariant
            g_tacc[i] = 0.0f;
        }
        st[tid] = make_float2(sv, tv);
    }
    __syncthreads();

    float w  = W1[f];
    float bb = b1[f];
    float a0 = 0.0f, a1 = 0.0f, a2 = 0.0f, a3 = 0.0f;

    // each quarter processes 128 nodes: 64 float4 loads = 128 (s,t) pairs
    const float4* stv = reinterpret_cast<const float4*>(st + qtr * 128);
    #pragma unroll
    for (int k = 0; k < 64; k += 2) {
        float4 p = stv[k];              // {s0,t0,s1,t1}
        float4 q = stv[k + 1];          // {s2,t2,s3,t3}
        float h0 = fmaxf(fmaf(p.x, w, bb), 0.0f);
        float h1 = fmaxf(fmaf(p.z, w, bb), 0.0f);
        float h2 = fmaxf(fmaf(q.x, w, bb), 0.0f);
        float h3 = fmaxf(fmaf(q.z, w, bb), 0.0f);
        a0 = fmaf(p.y, h0, a0);
        a1 = fmaf(p.w, h1, a1);
        a2 = fmaf(q.y, h2, a2);
        a3 = fmaf(q.w, h3, a3);
    }

    red[tid] = (a0 + a1) + (a2 + a3);
    __syncthreads();
    if (tid < HID)
        g_vpart[blockIdx.x * HID + f] =
            (red[f] + red[f + 128]) + (red[f + 256] + red[f + 384]);
}

// ---------------------------------------------------------------------------
// 5) reduce partials -> v[128]; out[o] = (1/N)*sum_f v[f]*W2[f,o] + b2[o]
__global__ void k_out(const float* __restrict__ W2, const float* __restrict__ b2,
                      float* __restrict__ out, int n, int nbv) {
    __shared__ float vsh[HID];
    __shared__ float tmp[512];
    const int tid = threadIdx.x;
    const int f   = tid & (HID - 1);
    const int grp = tid >> 7;           // 0..3

    float a = 0.0f;
    for (int b = grp; b < nbv; b += 4)
        a += g_vpart[b * HID + f];
    tmp[tid] = a;
    __syncthreads();
    if (tid < HID)
        vsh[tid] = (tmp[tid] + tmp[tid + 128]) + (tmp[tid + 256] + tmp[tid + 384]);
    __syncthreads();

    int o = tid;
    if (o < ODIM) {
        float acc = 0.0f;
        #pragma unroll 16
        for (int k = 0; k < HID; k++)
            acc = fmaf(vsh[k], W2[k * ODIM + o], acc);
        out[o] = acc * (1.0f / (float)n) + b2[o];
    }
}

// ---------------------------------------------------------------------------
extern "C" void kernel_launch(void* const* d_in, const int* in_sizes, int n_in,
                              void* d_out, int out_size) {
    const float* x  = (const float*)d_in[0];   // [N,1]
    const int*   ei = (const int*)d_in[1];     // [2,E]: row half then col half
    const float* W1 = (const float*)d_in[2];   // [1,128]
    const float* b1 = (const float*)d_in[3];   // [128]
    const float* W2 = (const float*)d_in[4];   // [128,400]
    const float* b2 = (const float*)d_in[5];   // [400]
    float* out = (float*)d_out;                // [400]

    int n = in_sizes[0];
    int E = in_sizes[1] / 2;
    const int* row = ei;
    const int* col = ei + E;
    int vec_ok = ((E & 3) == 0) ? 1 : 0;       // col half stays 16B-aligned

    int nb_n = (n + 255) / 256;
    int eth  = (E + 3) / 4;                    // 4 edges per thread
    int nb_e = (eth + 255) / 256;              // ~1563 blocks (R7-proven)
    int nb_v = (n + 511) / 512;                // 512-node tiles (~196 blocks)

    k_deg <<<nb_e, 256>>>(col, E, vec_ok);
    k_dinv<<<nb_n, 256>>>(x, n);
    k_edge<<<nb_e, 256>>>(row, col, E, vec_ok);
    k_v   <<<nb_v, 512>>>(W1, b1, n);
    k_out <<<1, 512>>>(W2, b2, out, n, nb_v);
}

// round 16
// speedup vs baseline: 1.1161x; 1.0048x over previous
#include <cuda_runtime.h>

#define MAXN 131072
#define HID  128
#define ODIM 400
#define MAXVB 512           // max k_v partial rows

// Scratch (no cudaMalloc allowed) — device globals, zeroed at module load.
// Consumers restore the zero-invariant so graph replays are deterministic.
__device__ unsigned g_degi[MAXN];
__device__ float    g_dinv[MAXN];
__device__ float    g_y[MAXN];      // y[r] = dinv[r] * x[r]
__device__ float    g_sacc[MAXN];
__device__ float    g_tacc[MAXN];
__device__ float    g_vpart[MAXVB * HID];   // per-block partials (no atomics)
__device__ unsigned g_vcnt;                 // completion counter (reset by last block)

// ---------------------------------------------------------------------------
// 1) degree count over destinations (col). R7-proven: 4 edges/thread, int4.
__global__ void __launch_bounds__(256, 8)
k_deg(const int* __restrict__ col, int E, int vec_ok) {
    int i = blockIdx.x * blockDim.x + threadIdx.x;
    int e = i * 4;
    if (vec_ok && e + 3 < E) {
        int4 c = *reinterpret_cast<const int4*>(col + e);
        atomicAdd(&g_degi[c.x], 1u);
        atomicAdd(&g_degi[c.y], 1u);
        atomicAdd(&g_degi[c.z], 1u);
        atomicAdd(&g_degi[c.w], 1u);
    } else if (e < E) {
        int lim = min(e + 4, E);
        for (int k = e; k < lim; k++) atomicAdd(&g_degi[col[k]], 1u);
    }
}

// ---------------------------------------------------------------------------
// 2) dinv = rsqrt(deg + 1 self loop); y = dinv * x; re-zero degi for replay.
__global__ void k_dinv(const float* __restrict__ x, int n) {
    int i = blockIdx.x * blockDim.x + threadIdx.x;
    if (i < n) {
        float di = rsqrtf((float)(g_degi[i] + 1u));
        g_dinv[i] = di;
        g_y[i]    = di * x[i];
        g_degi[i] = 0u;                 // restore entry invariant
    }
}

// ---------------------------------------------------------------------------
// 3) fused edge pass (R7-proven): independent gathers + fire-and-forget REDs.
//    sacc[c] += y[r];  tacc[r] += dinv[c]
__global__ void __launch_bounds__(256, 8)
k_edge(const int* __restrict__ row, const int* __restrict__ col,
       int E, int vec_ok) {
    int i = blockIdx.x * blockDim.x + threadIdx.x;
    int e = i * 4;
    if (vec_ok && e + 3 < E) {
        int4 r = *reinterpret_cast<const int4*>(row + e);
        int4 c = *reinterpret_cast<const int4*>(col + e);
        // 8 independent gathers (full MLP, L2-resident), then 8 REDs
        float y0 = __ldg(&g_y[r.x]);
        float y1 = __ldg(&g_y[r.y]);
        float y2 = __ldg(&g_y[r.z]);
        float y3 = __ldg(&g_y[r.w]);
        float d0 = __ldg(&g_dinv[c.x]);
        float d1 = __ldg(&g_dinv[c.y]);
        float d2 = __ldg(&g_dinv[c.z]);
        float d3 = __ldg(&g_dinv[c.w]);
        atomicAdd(&g_sacc[c.x], y0);
        atomicAdd(&g_sacc[c.y], y1);
        atomicAdd(&g_sacc[c.z], y2);
        atomicAdd(&g_sacc[c.w], y3);
        atomicAdd(&g_tacc[r.x], d0);
        atomicAdd(&g_tacc[r.y], d1);
        atomicAdd(&g_tacc[r.z], d2);
        atomicAdd(&g_tacc[r.w], d3);
    } else if (e < E) {
        int lim = min(e + 4, E);
        for (int k = e; k < lim; k++) {
            int r = row[k], c = col[k];
            atomicAdd(&g_sacc[c], __ldg(&g_y[r]));
            atomicAdd(&g_tacc[r], __ldg(&g_dinv[c]));
        }
    }
}

// ---------------------------------------------------------------------------
// 4) v[f] = sum_i t[i] * relu(s[i]*W1[f] + b1[f]); last block reduces the
//    partials and applies W2 (canonical threadFenceReduction pattern: the
//    fence is executed by ONE thread after __syncthreads — NOT by all
//    threads, which was the R13 regression).
//    s[i] = di*(sacc[i] + y[i]);  t[i] = di*(tacc[i] + di)
__global__ void __launch_bounds__(512, 4)
k_v(const float* __restrict__ W1, const float* __restrict__ b1,
    const float* __restrict__ W2, const float* __restrict__ b2,
    float* __restrict__ out, int n, int nbv) {
    __shared__ float2 st[512];          // {s, t} per node in tile
    __shared__ float  red[512];
    __shared__ unsigned s_last;
    const int tid = threadIdx.x;
    const int f   = tid & (HID - 1);
    const int qtr = tid >> 7;           // 0..3

    // tile load: 512 threads compute (s,t) for 512 nodes
    {
        int i = blockIdx.x * 512 + tid;
        float sv = 0.0f, tv = 0.0f;
        if (i < n) {
            float di = g_dinv[i];
            sv = di * (g_sacc[i] + g_y[i]);
            tv = di * (g_tacc[i] + di);
            g_sacc[i] = 0.0f;           // restore entry invariant
            g_tacc[i] = 0.0f;
        }
        st[tid] = make_float2(sv, tv);
    }
    __syncthreads();

    float w  = W1[f];
    float bb = b1[f];
    float a0 = 0.0f, a1 = 0.0f, a2 = 0.0f, a3 = 0.0f;

    // each quarter processes 128 nodes: 64 float4 loads = 128 (s,t) pairs
    const float4* stv = reinterpret_cast<const float4*>(st + qtr * 128);
    #pragma unroll
    for (int k = 0; k < 64; k += 2) {
        float4 p = stv[k];              // {s0,t0,s1,t1}
        float4 q = stv[k + 1];          // {s2,t2,s3,t3}
        float h0 = fmaxf(fmaf(p.x, w, bb), 0.0f);
        float h1 = fmaxf(fmaf(p.z, w, bb), 0.0f);
        float h2 = fmaxf(fmaf(q.x, w, bb), 0.0f);
        float h3 = fmaxf(fmaf(q.z, w, bb), 0.0f);
        a0 = fmaf(p.y, h0, a0);
        a1 = fmaf(p.w, h1, a1);
        a2 = fmaf(q.y, h2, a2);
        a3 = fmaf(q.w, h3, a3);
    }

    red[tid] = (a0 + a1) + (a2 + a3);
    __syncthreads();
    if (tid < HID)
        g_vpart[blockIdx.x * HID + f] =
            (red[f] + red[f + 128]) + (red[f + 256] + red[f + 384]);

    // ---- last-block-done epilogue (single-thread fence; replaces k_out) --
    __syncthreads();                    // vpart stores done block-wide
    if (tid == 0) {
        __threadfence();                // ONE fence per block (cheap)
        unsigned prev = atomicAdd(&g_vcnt, 1u);
        s_last = (prev == (unsigned)(nbv - 1)) ? 1u : 0u;
        if (s_last) {
            g_vcnt = 0u;                // restore entry invariant
            __threadfence();            // acquire-ish: order vpart reads after
        }
    }
    __syncthreads();
    if (!s_last) return;

    // reduce partials -> v[128]
    __shared__ float vsh[HID];
    float a = 0.0f;
    for (int b = qtr; b < nbv; b += 4)
        a += g_vpart[b * HID + f];
    red[tid] = a;
    __syncthreads();
    if (tid < HID)
        vsh[tid] = (red[tid] + red[tid + 128]) + (red[tid + 256] + red[tid + 384]);
    __syncthreads();

    // out[o] = (1/n) * sum_f v[f]*W2[f,o] + b2[o]
    if (tid < ODIM) {
        float acc = 0.0f;
        #pragma unroll 16
        for (int k = 0; k < HID; k++)
            acc = fmaf(vsh[k], W2[k * ODIM + tid], acc);
        out[tid] = acc * (1.0f / (float)n) + b2[tid];
    }
}

// ---------------------------------------------------------------------------
extern "C" void kernel_launch(void* const* d_in, const int* in_sizes, int n_in,
                              void* d_out, int out_size) {
    const float* x  = (const float*)d_in[0];   // [N,1]
    const int*   ei = (const int*)d_in[1];     // [2,E]: row half then col half
    const float* W1 = (const float*)d_in[2];   // [1,128]
    const float* b1 = (const float*)d_in[3];   // [128]
    const float* W2 = (const float*)d_in[4];   // [128,400]
    const float* b2 = (const float*)d_in[5];   // [400]
    float* out = (float*)d_out;                // [400]

    int n = in_sizes[0];
    int E = in_sizes[1] / 2;
    const int* row = ei;
    const int* col = ei + E;
    int vec_ok = ((E & 3) == 0) ? 1 : 0;       // col half stays 16B-aligned

    int nb_n = (n + 255) / 256;
    int eth  = (E + 3) / 4;                    // 4 edges per thread
    int nb_e = (eth + 255) / 256;              // ~1563 blocks (R7-proven)
    int nb_v = (n + 511) / 512;                // 512-node tiles (~196 blocks)

    k_deg <<<nb_e, 256>>>(col, E, vec_ok);
    k_dinv<<<nb_n, 256>>>(x, n);
    k_edge<<<nb_e, 256>>>(row, col, E, vec_ok);
    k_v   <<<nb_v, 512>>>(W1, b1, W2, b2, out, n, nb_v);
}